// round 2
// baseline (speedup 1.0000x reference)
#include <cuda_runtime.h>
#include <math_constants.h>

#define N 8192
#define D 512

// ---------------- device scratch (no allocations allowed) ----------------
__device__ __align__(256) float d_Cxy[67108864];   // dist(xs, xt)   256MB
__device__ __align__(256) float d_Cyx[67108864];   // transpose      256MB
__device__ __align__(256) float d_Cxx[67108864];   // dist(xs, xs)   256MB
__device__ __align__(256) float d_Cyy[67108864];   // dist(xt, xt)   256MB
__device__ __align__(256) float d_sx[N];
__device__ __align__(256) float d_sy[N];
__device__ __align__(256) float d_vecs[2][4][N];   // ping-pong f,g,p,q
__device__ __align__(256) float d_evec[4][N];      // f_e, g_e, p_e, q_e

// constants
// Kc = 1/(eps*ln2): scale (v - C) into base-2 exponent domain
#define KC        28.85390081777927f
#define EPSLN2    0.034657359027997264f   // eps*ln2
#define EPSLOGN   0.4505456673639644f     // eps*ln(8192)

// ---------------- row squared-norms ----------------
__global__ void rownorm_kernel(const float* __restrict__ X, const float* __restrict__ PZ) {
    const float* src = (blockIdx.y == 0) ? PZ : X;    // y=0: xs=prior_z -> sx
    float* dst = (blockIdx.y == 0) ? d_sx : d_sy;
    int row = blockIdx.x * 8 + (threadIdx.x >> 5);
    int lane = threadIdx.x & 31;
    const float4* xr = (const float4*)(src + (size_t)row * D);
    float s = 0.f;
    #pragma unroll
    for (int t = lane; t < D / 4; t += 32) {
        float4 v = xr[t];
        s += v.x * v.x + v.y * v.y + v.z * v.z + v.w * v.w;
    }
    #pragma unroll
    for (int o = 16; o; o >>= 1) s += __shfl_down_sync(0xffffffffu, s, o);
    if (lane == 0) dst[row] = s;
}

__global__ void init_kernel() {
    int i = blockIdx.x * blockDim.x + threadIdx.x;
    if (i < 2 * 4 * N) ((float*)d_vecs)[i] = 0.f;
}

// ---------------- fused GEMM + distance ----------------
// C[i][j] = sqrt(max(sA[i] + sB[j] - 2*dot(A_i, B_j), 1e-12))
// which=0: Cxy (+ Cyx transpose), which=1: Cxx (sym), which=2: Cyy (sym)
__global__ __launch_bounds__(256) void gemm_dist_kernel(
    const float* __restrict__ X, const float* __restrict__ PZ, int which)
{
    const float *A, *B, *sA, *sB;
    float *C, *Cm;
    bool sym;
    if (which == 0)      { A = PZ; B = X;  sA = d_sx; sB = d_sy; C = d_Cxy; Cm = d_Cyx; sym = false; }
    else if (which == 1) { A = PZ; B = PZ; sA = d_sx; sB = d_sx; C = d_Cxx; Cm = d_Cxx; sym = true;  }
    else                 { A = X;  B = X;  sA = d_sy; sB = d_sy; C = d_Cyy; Cm = d_Cyy; sym = true;  }

    int bx = blockIdx.x, by = blockIdx.y;
    if (sym && by > bx) return;   // upper-triangular tiles only; mirror-write the rest

    __shared__ float As[16][132];
    __shared__ float Bs[16][132];
    int tid = threadIdx.x;
    int ty = tid >> 4, tx = tid & 15;
    int trow = ty * 8, tcol = tx * 8;

    float acc[8][8];
    #pragma unroll
    for (int i = 0; i < 8; i++)
        #pragma unroll
        for (int j = 0; j < 8; j++) acc[i][j] = 0.f;

    const float* Ab = A + (size_t)by * 128 * D;
    const float* Bb = B + (size_t)bx * 128 * D;

    for (int k0 = 0; k0 < D; k0 += 16) {
        #pragma unroll
        for (int l = 0; l < 2; l++) {
            int idx = tid + l * 256;       // 0..511
            int r = idx >> 2;              // 0..127
            int c = (idx & 3) << 2;        // 0,4,8,12
            float4 av = *(const float4*)(Ab + (size_t)r * D + k0 + c);
            As[c + 0][r] = av.x; As[c + 1][r] = av.y; As[c + 2][r] = av.z; As[c + 3][r] = av.w;
            float4 bv = *(const float4*)(Bb + (size_t)r * D + k0 + c);
            Bs[c + 0][r] = bv.x; Bs[c + 1][r] = bv.y; Bs[c + 2][r] = bv.z; Bs[c + 3][r] = bv.w;
        }
        __syncthreads();
        #pragma unroll
        for (int kk = 0; kk < 16; kk++) {
            float ar[8], br[8];
            #pragma unroll
            for (int i = 0; i < 8; i++) ar[i] = As[kk][trow + i];
            #pragma unroll
            for (int j = 0; j < 8; j++) br[j] = Bs[kk][tcol + j];
            #pragma unroll
            for (int i = 0; i < 8; i++)
                #pragma unroll
                for (int j = 0; j < 8; j++)
                    acc[i][j] = fmaf(ar[i], br[j], acc[i][j]);
        }
        __syncthreads();
    }

    int gr = by * 128 + trow, gc = bx * 128 + tcol;
    float sa[8], sb[8];
    #pragma unroll
    for (int i = 0; i < 8; i++) sa[i] = sA[gr + i];
    #pragma unroll
    for (int j = 0; j < 8; j++) sb[j] = sB[gc + j];

    #pragma unroll
    for (int i = 0; i < 8; i++) {
        float tmp[8];
        #pragma unroll
        for (int j = 0; j < 8; j++) {
            float sq = sa[i] + sb[j] - 2.f * acc[i][j];
            tmp[j] = sqrtf(fmaxf(sq, 1e-12f));
        }
        *(float4*)&C[(size_t)(gr + i) * N + gc]     = make_float4(tmp[0], tmp[1], tmp[2], tmp[3]);
        *(float4*)&C[(size_t)(gr + i) * N + gc + 4] = make_float4(tmp[4], tmp[5], tmp[6], tmp[7]);
        #pragma unroll
        for (int j = 0; j < 8; j++)
            Cm[(size_t)(gc + j) * N + gr + i] = tmp[j];   // transpose / mirror (same value when overlapping)
    }
}

// ---------------- per-row online logsumexp update ----------------
// mode=0: damped Sinkhorn update (writes d_vecs[parity^1])
// mode=1: extrapolation (writes d_evec)
__global__ void lse_kernel(int parity, int mode) {
    int row = blockIdx.x;
    int which = blockIdx.y;

    const float* base_r = &d_vecs[parity][0][0];
    float* base_w = &d_vecs[parity ^ 1][0][0];
    const float* C; const float* vin; const float* vold; float* vout;
    if (which == 0)      { C = d_Cxy; vin = base_r + N;     vold = base_r;         vout = base_w;         }
    else if (which == 1) { C = d_Cyx; vin = base_r;         vold = base_r + N;     vout = base_w + N;     }
    else if (which == 2) { C = d_Cxx; vin = base_r + 2 * N; vold = base_r + 2 * N; vout = base_w + 2 * N; }
    else                 { C = d_Cyy; vin = base_r + 3 * N; vold = base_r + 3 * N; vout = base_w + 3 * N; }
    if (mode) vout = &d_evec[which][0];

    const float4* Cr = (const float4*)(C + (size_t)row * N);
    const float4* V  = (const float4*)vin;

    float mx = -CUDART_INF_F, s = 0.f;
    #define ONLINE(a) { if ((a) <= mx) s += exp2f((a) - mx); \
                        else { s = fmaf(s, exp2f(mx - (a)), 1.f); mx = (a); } }
    for (int t = threadIdx.x; t < N / 4; t += 256) {
        float4 c = Cr[t]; float4 v = V[t];
        float a0 = (v.x - c.x) * KC;
        float a1 = (v.y - c.y) * KC;
        float a2 = (v.z - c.z) * KC;
        float a3 = (v.w - c.w) * KC;
        ONLINE(a0); ONLINE(a1); ONLINE(a2); ONLINE(a3);
    }
    #undef ONLINE

    // warp merge
    #pragma unroll
    for (int o = 16; o; o >>= 1) {
        float m2 = __shfl_down_sync(0xffffffffu, mx, o);
        float s2 = __shfl_down_sync(0xffffffffu, s, o);
        float M = fmaxf(mx, m2);
        s = s * exp2f(mx - M) + s2 * exp2f(m2 - M);
        mx = M;
    }
    __shared__ float sm[8], ss[8];
    int w = threadIdx.x >> 5, lane = threadIdx.x & 31;
    if (lane == 0) { sm[w] = mx; ss[w] = s; }
    __syncthreads();
    if (threadIdx.x == 0) {
        float M = sm[0], S = ss[0];
        #pragma unroll
        for (int i = 1; i < 8; i++) {
            float M2 = fmaxf(M, sm[i]);
            S = S * exp2f(M - M2) + ss[i] * exp2f(sm[i] - M2);
            M = M2;
        }
        float lse2 = M + log2f(S);   // base-2 LSE of scaled values
        float val;
        if (mode) val = EPSLOGN - EPSLN2 * lse2;
        else      val = 0.5f * (vold[row] + EPSLOGN - EPSLN2 * lse2);
        vout[row] = val;
    }
}

// ---------------- final scalar reduction ----------------
__global__ void final_kernel(float* out) {
    __shared__ double sh[32];
    double acc = 0.0;
    for (int i = threadIdx.x; i < N; i += 1024) {
        acc += (double)d_evec[0][i] - (double)d_evec[2][i]
             + (double)d_evec[1][i] - (double)d_evec[3][i];
    }
    #pragma unroll
    for (int o = 16; o; o >>= 1) acc += __shfl_down_sync(0xffffffffu, acc, o);
    int w = threadIdx.x >> 5, lane = threadIdx.x & 31;
    if (lane == 0) sh[w] = acc;
    __syncthreads();
    if (threadIdx.x < 32) {
        double a = sh[threadIdx.x];
        #pragma unroll
        for (int o = 16; o; o >>= 1) a += __shfl_down_sync(0xffffffffu, a, o);
        if (threadIdx.x == 0) out[0] = (float)(a / (double)N);
    }
}

// ---------------- launch ----------------
extern "C" void kernel_launch(void* const* d_in, const int* in_sizes, int n_in,
                              void* d_out, int out_size) {
    (void)in_sizes; (void)n_in; (void)out_size;
    const float* x  = (const float*)d_in[0];   // xt
    const float* pz = (const float*)d_in[1];   // xs

    rownorm_kernel<<<dim3(N / 8, 2), 256>>>(x, pz);
    init_kernel<<<(2 * 4 * N + 255) / 256, 256>>>();

    dim3 gg(64, 64);
    gemm_dist_kernel<<<gg, 256>>>(x, pz, 0);
    gemm_dist_kernel<<<gg, 256>>>(x, pz, 1);
    gemm_dist_kernel<<<gg, 256>>>(x, pz, 2);

    for (int it = 0; it < 50; ++it)
        lse_kernel<<<dim3(N, 4), 256>>>(it & 1, 0);

    lse_kernel<<<dim3(N, 4), 256>>>(0, 1);       // extrapolation (final vecs are in slot 0)
    final_kernel<<<1, 1024>>>((float*)d_out);
}

// round 4
// speedup vs baseline: 1.3928x; 1.3928x over previous
#include <cuda_runtime.h>
#include <math_constants.h>

#define N 8192
#define D 512

// quantization: C stored as uint16, value = q / QSCALE, QSCALE = 1600 (max 40.96)
#define QSCALE    1600.0f
// KC = 1/(eps*ln2) converts cost units to base-2 exponent units
#define KC        28.85390081777927f
#define QK        (KC / QSCALE)               // 0.0180336880111f
#define EPSLN2    0.034657359027997264f       // eps*ln2
#define EPSLOGN   0.4505456673639644f         // eps*ln(8192)

// ---------------- device scratch (no allocations allowed) ----------------
__device__ __align__(256) unsigned short d_Cxy[67108864];   // 128MB each
__device__ __align__(256) unsigned short d_Cyx[67108864];
__device__ __align__(256) unsigned short d_Cxx[67108864];
__device__ __align__(256) unsigned short d_Cyy[67108864];
__device__ __align__(256) float d_sx[N];
__device__ __align__(256) float d_sy[N];
__device__ __align__(256) float d_vecs[2][4][N];   // ping-pong f,g,p,q
__device__ __align__(256) float d_evec[4][N];      // f_e, g_e, p_e, q_e

// ---------------- row squared-norms ----------------
__global__ void rownorm_kernel(const float* __restrict__ X, const float* __restrict__ PZ) {
    const float* src = (blockIdx.y == 0) ? PZ : X;    // y=0: xs=prior_z -> sx
    float* dst = (blockIdx.y == 0) ? d_sx : d_sy;
    int row = blockIdx.x * 8 + (threadIdx.x >> 5);
    int lane = threadIdx.x & 31;
    const float4* xr = (const float4*)(src + (size_t)row * D);
    float s = 0.f;
    #pragma unroll
    for (int t = lane; t < D / 4; t += 32) {
        float4 v = xr[t];
        s += v.x * v.x + v.y * v.y + v.z * v.z + v.w * v.w;
    }
    #pragma unroll
    for (int o = 16; o; o >>= 1) s += __shfl_down_sync(0xffffffffu, s, o);
    if (lane == 0) dst[row] = s;
}

__global__ void init_kernel() {
    int i = blockIdx.x * blockDim.x + threadIdx.x;
    if (i < 2 * 4 * N) ((float*)d_vecs)[i] = 0.f;
}

// ---------------- fused GEMM + distance + uint16 quantize ----------------
// C[i][j] = sqrt(max(sA[i] + sB[j] - 2*dot(A_i, B_j), 1e-12)), stored quantized.
// which=0: Cxy (+ Cyx transpose), which=1: Cxx (sym), which=2: Cyy (sym)
__global__ __launch_bounds__(256) void gemm_dist_kernel(
    const float* __restrict__ X, const float* __restrict__ PZ, int which)
{
    const float *A, *B, *sA, *sB;
    unsigned short *C, *Cm;
    bool sym;
    if (which == 0)      { A = PZ; B = X;  sA = d_sx; sB = d_sy; C = d_Cxy; Cm = d_Cyx; sym = false; }
    else if (which == 1) { A = PZ; B = PZ; sA = d_sx; sB = d_sx; C = d_Cxx; Cm = d_Cxx; sym = true;  }
    else                 { A = X;  B = X;  sA = d_sy; sB = d_sy; C = d_Cyy; Cm = d_Cyy; sym = true;  }

    int bx = blockIdx.x, by = blockIdx.y;
    if (sym && by > bx) return;   // triangular tiles only; mirror via transpose store

    __shared__ float As[16][132];
    __shared__ float Bs[16][132];
    __shared__ unsigned int ts[128][65];   // packed uint16 pairs, pad->conflict-free cols

    int tid = threadIdx.x;
    int ty = tid >> 4, tx = tid & 15;
    int trow = ty * 8, tcol = tx * 8;

    float acc[8][8];
    #pragma unroll
    for (int i = 0; i < 8; i++)
        #pragma unroll
        for (int j = 0; j < 8; j++) acc[i][j] = 0.f;

    const float* Ab = A + (size_t)by * 128 * D;
    const float* Bb = B + (size_t)bx * 128 * D;

    for (int k0 = 0; k0 < D; k0 += 16) {
        #pragma unroll
        for (int l = 0; l < 2; l++) {
            int idx = tid + l * 256;       // 0..511
            int r = idx >> 2;              // 0..127
            int c = (idx & 3) << 2;        // 0,4,8,12
            float4 av = *(const float4*)(Ab + (size_t)r * D + k0 + c);
            As[c + 0][r] = av.x; As[c + 1][r] = av.y; As[c + 2][r] = av.z; As[c + 3][r] = av.w;
            float4 bv = *(const float4*)(Bb + (size_t)r * D + k0 + c);
            Bs[c + 0][r] = bv.x; Bs[c + 1][r] = bv.y; Bs[c + 2][r] = bv.z; Bs[c + 3][r] = bv.w;
        }
        __syncthreads();
        #pragma unroll
        for (int kk = 0; kk < 16; kk++) {
            float ar[8], br[8];
            #pragma unroll
            for (int i = 0; i < 8; i++) ar[i] = As[kk][trow + i];
            #pragma unroll
            for (int j = 0; j < 8; j++) br[j] = Bs[kk][tcol + j];
            #pragma unroll
            for (int i = 0; i < 8; i++)
                #pragma unroll
                for (int j = 0; j < 8; j++)
                    acc[i][j] = fmaf(ar[i], br[j], acc[i][j]);
        }
        __syncthreads();
    }

    int gr0 = by * 128, gc0 = bx * 128;
    float sa[8], sb[8];
    #pragma unroll
    for (int i = 0; i < 8; i++) sa[i] = sA[gr0 + trow + i];
    #pragma unroll
    for (int j = 0; j < 8; j++) sb[j] = sB[gc0 + tcol + j];

    // quantize into smem tile (packed pairs)
    #pragma unroll
    for (int i = 0; i < 8; i++) {
        #pragma unroll
        for (int j = 0; j < 8; j += 2) {
            float sq0 = sa[i] + sb[j]     - 2.f * acc[i][j];
            float sq1 = sa[i] + sb[j + 1] - 2.f * acc[i][j + 1];
            float d0 = sqrtf(fmaxf(sq0, 1e-12f));
            float d1 = sqrtf(fmaxf(sq1, 1e-12f));
            unsigned int q0 = min(65535u, __float2uint_rn(d0 * QSCALE));
            unsigned int q1 = min(65535u, __float2uint_rn(d1 * QSCALE));
            ts[trow + i][(tcol + j) >> 1] = q0 | (q1 << 16);
        }
    }
    __syncthreads();

    // coalesced C row stores
    for (int idx = tid; idx < 128 * 16; idx += 256) {
        int r = idx >> 4, seg = idx & 15;
        uint4 w;
        w.x = ts[r][seg * 4 + 0];
        w.y = ts[r][seg * 4 + 1];
        w.z = ts[r][seg * 4 + 2];
        w.w = ts[r][seg * 4 + 3];
        *(uint4*)&C[(size_t)(gr0 + r) * N + gc0 + seg * 8] = w;
    }
    // coalesced transpose/mirror row stores
    for (int idx = tid; idx < 128 * 16; idx += 256) {
        int c = idx >> 4, seg = idx & 15;
        uint4 w;
        unsigned int sh = (c & 1) * 16;
        #pragma unroll
        for (int k = 0; k < 4; k++) {
            int r = seg * 8 + k * 2;
            unsigned int lo = (ts[r][c >> 1] >> sh) & 0xFFFFu;
            unsigned int hi = (ts[r + 1][c >> 1] >> sh) & 0xFFFFu;
            ((unsigned int*)&w)[k] = lo | (hi << 16);
        }
        *(uint4*)&Cm[(size_t)(gc0 + c) * N + gr0 + seg * 8] = w;
    }
}

// ---------------- per-row logsumexp update (two-phase, register-buffered) ----
// mode=0: damped Sinkhorn update (writes d_vecs[parity^1]); mode=1: extrapolation
__global__ __launch_bounds__(256) void lse_kernel(int parity, int mode) {
    int row = blockIdx.x;
    int which = blockIdx.y;

    const float* base_r = &d_vecs[parity][0][0];
    float* base_w = &d_vecs[parity ^ 1][0][0];
    const unsigned short* Cq; const float* vin; const float* vold; float* vout;
    if (which == 0)      { Cq = d_Cxy; vin = base_r + N;     vold = base_r;         vout = base_w;         }
    else if (which == 1) { Cq = d_Cyx; vin = base_r;         vold = base_r + N;     vout = base_w + N;     }
    else if (which == 2) { Cq = d_Cxx; vin = base_r + 2 * N; vold = base_r + 2 * N; vout = base_w + 2 * N; }
    else                 { Cq = d_Cyy; vin = base_r + 3 * N; vold = base_r + 3 * N; vout = base_w + 3 * N; }
    if (mode) vout = &d_evec[which][0];

    const uint4* Cr = (const uint4*)(Cq + (size_t)row * N);   // 1024 uint4 (8 elems each)
    const float4* V = (const float4*)vin;

    const float nQK = -QK;
    const float BIG = QK * 8388608.0f;   // exact: QK mantissa * 2^23

    float a[32];
    float mx = -CUDART_INF_F;

    #pragma unroll
    for (int it = 0; it < 4; it++) {
        int base = it * 256 + threadIdx.x;      // coalesced: warp spans 512B
        uint4 u = Cr[base];
        float4 v0 = V[base * 2];
        float4 v1 = V[base * 2 + 1];
        #define UNP(uw, va, vb, i0) { \
            float q0 = __uint_as_float(0x4B000000u | ((uw) & 0xFFFFu)); \
            float q1 = __uint_as_float(0x4B000000u | ((uw) >> 16)); \
            float t0 = fmaf(q0, nQK, BIG); \
            float t1 = fmaf(q1, nQK, BIG); \
            float a0 = fmaf((va), KC, t0); \
            float a1 = fmaf((vb), KC, t1); \
            a[(i0)] = a0; a[(i0) + 1] = a1; \
            mx = fmaxf(mx, fmaxf(a0, a1)); }
        UNP(u.x, v0.x, v0.y, it * 8 + 0)
        UNP(u.y, v0.z, v0.w, it * 8 + 2)
        UNP(u.z, v1.x, v1.y, it * 8 + 4)
        UNP(u.w, v1.z, v1.w, it * 8 + 6)
        #undef UNP
    }

    // block max reduction + broadcast
    __shared__ float sm[8];
    __shared__ float ssum[8];
    int w = threadIdx.x >> 5, lane = threadIdx.x & 31;
    float m = mx;
    #pragma unroll
    for (int o = 16; o; o >>= 1) m = fmaxf(m, __shfl_xor_sync(0xffffffffu, m, o));
    if (lane == 0) sm[w] = m;
    __syncthreads();
    float Mx = sm[0];
    #pragma unroll
    for (int i = 1; i < 8; i++) Mx = fmaxf(Mx, sm[i]);

    // thresholded exp sum (skip contributions < 2^-25)
    float thr = Mx - 25.f;
    float s = 0.f;
    #pragma unroll
    for (int k = 0; k < 32; k++) {
        if (a[k] > thr) s += exp2f(a[k] - Mx);
    }
    #pragma unroll
    for (int o = 16; o; o >>= 1) s += __shfl_xor_sync(0xffffffffu, s, o);
    if (lane == 0) ssum[w] = s;
    __syncthreads();

    if (threadIdx.x == 0) {
        float S = ssum[0];
        #pragma unroll
        for (int i = 1; i < 8; i++) S += ssum[i];
        float lse2 = Mx + log2f(S);            // base-2 LSE of scaled values
        float val;
        if (mode) val = EPSLOGN - EPSLN2 * lse2;
        else      val = 0.5f * (vold[row] + EPSLOGN - EPSLN2 * lse2);
        vout[row] = val;
    }
}

// ---------------- final scalar reduction ----------------
__global__ void final_kernel(float* out) {
    __shared__ double sh[32];
    double acc = 0.0;
    for (int i = threadIdx.x; i < N; i += 1024) {
        acc += (double)d_evec[0][i] - (double)d_evec[2][i]
             + (double)d_evec[1][i] - (double)d_evec[3][i];
    }
    #pragma unroll
    for (int o = 16; o; o >>= 1) acc += __shfl_down_sync(0xffffffffu, acc, o);
    int w = threadIdx.x >> 5, lane = threadIdx.x & 31;
    if (lane == 0) sh[w] = acc;
    __syncthreads();
    if (threadIdx.x < 32) {
        double a = sh[threadIdx.x];
        #pragma unroll
        for (int o = 16; o; o >>= 1) a += __shfl_down_sync(0xffffffffu, a, o);
        if (threadIdx.x == 0) out[0] = (float)(a / (double)N);
    }
}

// ---------------- launch ----------------
extern "C" void kernel_launch(void* const* d_in, const int* in_sizes, int n_in,
                              void* d_out, int out_size) {
    (void)in_sizes; (void)n_in; (void)out_size;
    const float* x  = (const float*)d_in[0];   // xt
    const float* pz = (const float*)d_in[1];   // xs

    rownorm_kernel<<<dim3(N / 8, 2), 256>>>(x, pz);
    init_kernel<<<(2 * 4 * N + 255) / 256, 256>>>();

    dim3 gg(64, 64);
    gemm_dist_kernel<<<gg, 256>>>(x, pz, 0);
    gemm_dist_kernel<<<gg, 256>>>(x, pz, 1);
    gemm_dist_kernel<<<gg, 256>>>(x, pz, 2);

    for (int it = 0; it < 50; ++it)
        lse_kernel<<<dim3(N, 4), 256>>>(it & 1, 0);

    lse_kernel<<<dim3(N, 4), 256>>>(0, 1);       // extrapolation (final vecs in slot 0)
    final_kernel<<<1, 1024>>>((float*)d_out);
}

// round 6
// speedup vs baseline: 1.7143x; 1.2308x over previous
#include <cuda_runtime.h>
#include <math_constants.h>

#define N 8192
#define D 512
#define ROWS 8   // rows per LSE block

// quantization: C stored as uint16, value = q / QSCALE, QSCALE = 1600 (max 40.96)
#define QSCALE    1600.0f
// KC = 1/(eps*ln2) converts cost units to base-2 exponent units
#define KC        28.85390081777927f
#define QK        (KC / QSCALE)               // 0.0180336880111f
#define EPSLN2    0.034657359027997264f       // eps*ln2
#define EPSLOGN   0.4505456673639644f         // eps*ln(8192)

// ---------------- device scratch (no allocations allowed) ----------------
__device__ __align__(256) unsigned short d_Cxy[67108864];   // 128MB each
__device__ __align__(256) unsigned short d_Cyx[67108864];
__device__ __align__(256) unsigned short d_Cxx[67108864];
__device__ __align__(256) unsigned short d_Cyy[67108864];
__device__ __align__(256) float d_sx[N];
__device__ __align__(256) float d_sy[N];
__device__ __align__(256) float d_vecs[2][4][N];   // ping-pong f,g,p,q
__device__ __align__(256) float d_evec[4][N];      // f_e, g_e, p_e, q_e

// ---------------- row squared-norms ----------------
__global__ void rownorm_kernel(const float* __restrict__ X, const float* __restrict__ PZ) {
    const float* src = (blockIdx.y == 0) ? PZ : X;    // y=0: xs=prior_z -> sx
    float* dst = (blockIdx.y == 0) ? d_sx : d_sy;
    int row = blockIdx.x * 8 + (threadIdx.x >> 5);
    int lane = threadIdx.x & 31;
    const float4* xr = (const float4*)(src + (size_t)row * D);
    float s = 0.f;
    #pragma unroll
    for (int t = lane; t < D / 4; t += 32) {
        float4 v = xr[t];
        s += v.x * v.x + v.y * v.y + v.z * v.z + v.w * v.w;
    }
    #pragma unroll
    for (int o = 16; o; o >>= 1) s += __shfl_down_sync(0xffffffffu, s, o);
    if (lane == 0) dst[row] = s;
}

__global__ void init_kernel() {
    int i = blockIdx.x * blockDim.x + threadIdx.x;
    if (i < 2 * 4 * N) ((float*)d_vecs)[i] = 0.f;
}

// ---------------- fused GEMM + distance + uint16 quantize ----------------
__global__ __launch_bounds__(256) void gemm_dist_kernel(
    const float* __restrict__ X, const float* __restrict__ PZ, int which)
{
    const float *A, *B, *sA, *sB;
    unsigned short *C, *Cm;
    bool sym;
    if (which == 0)      { A = PZ; B = X;  sA = d_sx; sB = d_sy; C = d_Cxy; Cm = d_Cyx; sym = false; }
    else if (which == 1) { A = PZ; B = PZ; sA = d_sx; sB = d_sx; C = d_Cxx; Cm = d_Cxx; sym = true;  }
    else                 { A = X;  B = X;  sA = d_sy; sB = d_sy; C = d_Cyy; Cm = d_Cyy; sym = true;  }

    int bx = blockIdx.x, by = blockIdx.y;
    if (sym && by > bx) return;   // triangular tiles only; mirror via transpose store

    __shared__ float As[16][132];
    __shared__ float Bs[16][132];
    __shared__ unsigned int ts[128][65];   // packed uint16 pairs, pad->conflict-free cols

    int tid = threadIdx.x;
    int ty = tid >> 4, tx = tid & 15;
    int trow = ty * 8, tcol = tx * 8;

    float acc[8][8];
    #pragma unroll
    for (int i = 0; i < 8; i++)
        #pragma unroll
        for (int j = 0; j < 8; j++) acc[i][j] = 0.f;

    const float* Ab = A + (size_t)by * 128 * D;
    const float* Bb = B + (size_t)bx * 128 * D;

    for (int k0 = 0; k0 < D; k0 += 16) {
        #pragma unroll
        for (int l = 0; l < 2; l++) {
            int idx = tid + l * 256;       // 0..511
            int r = idx >> 2;              // 0..127
            int c = (idx & 3) << 2;        // 0,4,8,12
            float4 av = *(const float4*)(Ab + (size_t)r * D + k0 + c);
            As[c + 0][r] = av.x; As[c + 1][r] = av.y; As[c + 2][r] = av.z; As[c + 3][r] = av.w;
            float4 bv = *(const float4*)(Bb + (size_t)r * D + k0 + c);
            Bs[c + 0][r] = bv.x; Bs[c + 1][r] = bv.y; Bs[c + 2][r] = bv.z; Bs[c + 3][r] = bv.w;
        }
        __syncthreads();
        #pragma unroll
        for (int kk = 0; kk < 16; kk++) {
            float ar[8], br[8];
            #pragma unroll
            for (int i = 0; i < 8; i++) ar[i] = As[kk][trow + i];
            #pragma unroll
            for (int j = 0; j < 8; j++) br[j] = Bs[kk][tcol + j];
            #pragma unroll
            for (int i = 0; i < 8; i++)
                #pragma unroll
                for (int j = 0; j < 8; j++)
                    acc[i][j] = fmaf(ar[i], br[j], acc[i][j]);
        }
        __syncthreads();
    }

    int gr0 = by * 128, gc0 = bx * 128;
    float sa[8], sb[8];
    #pragma unroll
    for (int i = 0; i < 8; i++) sa[i] = sA[gr0 + trow + i];
    #pragma unroll
    for (int j = 0; j < 8; j++) sb[j] = sB[gc0 + tcol + j];

    #pragma unroll
    for (int i = 0; i < 8; i++) {
        #pragma unroll
        for (int j = 0; j < 8; j += 2) {
            float sq0 = sa[i] + sb[j]     - 2.f * acc[i][j];
            float sq1 = sa[i] + sb[j + 1] - 2.f * acc[i][j + 1];
            float d0 = sqrtf(fmaxf(sq0, 1e-12f));
            float d1 = sqrtf(fmaxf(sq1, 1e-12f));
            unsigned int q0 = min(65535u, __float2uint_rn(d0 * QSCALE));
            unsigned int q1 = min(65535u, __float2uint_rn(d1 * QSCALE));
            ts[trow + i][(tcol + j) >> 1] = q0 | (q1 << 16);
        }
    }
    __syncthreads();

    for (int idx = tid; idx < 128 * 16; idx += 256) {
        int r = idx >> 4, seg = idx & 15;
        uint4 w;
        w.x = ts[r][seg * 4 + 0];
        w.y = ts[r][seg * 4 + 1];
        w.z = ts[r][seg * 4 + 2];
        w.w = ts[r][seg * 4 + 3];
        *(uint4*)&C[(size_t)(gr0 + r) * N + gc0 + seg * 8] = w;
    }
    for (int idx = tid; idx < 128 * 16; idx += 256) {
        int c = idx >> 4, seg = idx & 15;
        uint4 w;
        unsigned int sh = (c & 1) * 16;
        #pragma unroll
        for (int k = 0; k < 4; k++) {
            int r = seg * 8 + k * 2;
            unsigned int lo = (ts[r][c >> 1] >> sh) & 0xFFFFu;
            unsigned int hi = (ts[r + 1][c >> 1] >> sh) & 0xFFFFu;
            ((unsigned int*)&w)[k] = lo | (hi << 16);
        }
        *(uint4*)&Cm[(size_t)(gc0 + c) * N + gr0 + seg * 8] = w;
    }
}

// ---------------- multi-row logsumexp update ----------------
// 8 rows per block. V operand cached in registers (same columns each row).
// C rows double-buffered. exp pass guarded by warp vote.
// mode=0: damped Sinkhorn update; mode=1: extrapolation
__global__ __launch_bounds__(256) void lse_kernel(int parity, int mode) {
    int row0 = blockIdx.x * ROWS;
    int which = blockIdx.y;
    int tid = threadIdx.x;

    const float* base_r = &d_vecs[parity][0][0];
    float* base_w = &d_vecs[parity ^ 1][0][0];
    const unsigned short* Cq; const float* vin; const float* vold; float* vout;
    if (which == 0)      { Cq = d_Cxy; vin = base_r + N;     vold = base_r;         vout = base_w;         }
    else if (which == 1) { Cq = d_Cyx; vin = base_r;         vold = base_r + N;     vout = base_w + N;     }
    else if (which == 2) { Cq = d_Cxx; vin = base_r + 2 * N; vold = base_r + 2 * N; vout = base_w + 2 * N; }
    else                 { Cq = d_Cyy; vin = base_r + 3 * N; vold = base_r + 3 * N; vout = base_w + 3 * N; }
    if (mode) vout = &d_evec[which][0];

    const float nQK = -QK;
    const float BIG = QK * 8388608.0f;     // exact: QK * 2^23 (decode bias)
    const float4* V4 = (const float4*)vin;

    // V operand in registers: thread t owns columns {8*(it*256+t) .. +7}, it=0..3
    float vr[4][8];
    #pragma unroll
    for (int it = 0; it < 4; it++) {
        int base = it * 256 + tid;
        float4 v0 = V4[base * 2];
        float4 v1 = V4[base * 2 + 1];
        vr[it][0] = v0.x; vr[it][1] = v0.y; vr[it][2] = v0.z; vr[it][3] = v0.w;
        vr[it][4] = v1.x; vr[it][5] = v1.y; vr[it][6] = v1.z; vr[it][7] = v1.w;
    }

    const unsigned short* Cb = Cq + (size_t)row0 * N;
    uint4 cur[4], nxt[4];
    #pragma unroll
    for (int it = 0; it < 4; it++)
        cur[it] = ((const uint4*)Cb)[it * 256 + tid];

    __shared__ float sm[8];
    __shared__ float ssum[8];
    int w = tid >> 5, lane = tid & 31;

    // decode: a0,a1 for packed pair uw against v values va,vb
    #define DEC2(uw, va, vb, a0, a1) \
        { float q0 = __uint_as_float(0x4B000000u | ((uw) & 0xFFFFu)); \
          float q1 = __uint_as_float(0x4B000000u | ((uw) >> 16)); \
          a0 = fmaf((va), KC, fmaf(q0, nQK, BIG)); \
          a1 = fmaf((vb), KC, fmaf(q1, nQK, BIG)); }

    for (int r = 0; r < ROWS; r++) {
        if (r + 1 < ROWS) {
            const uint4* Cn = (const uint4*)(Cb + (size_t)(r + 1) * N);
            #pragma unroll
            for (int it = 0; it < 4; it++) nxt[it] = Cn[it * 256 + tid];
        }

        // pass 1: max
        float m = -CUDART_INF_F;
        #pragma unroll
        for (int it = 0; it < 4; it++) {
            float a0, a1;
            DEC2(cur[it].x, vr[it][0], vr[it][1], a0, a1); m = fmaxf(m, fmaxf(a0, a1));
            DEC2(cur[it].y, vr[it][2], vr[it][3], a0, a1); m = fmaxf(m, fmaxf(a0, a1));
            DEC2(cur[it].z, vr[it][4], vr[it][5], a0, a1); m = fmaxf(m, fmaxf(a0, a1));
            DEC2(cur[it].w, vr[it][6], vr[it][7], a0, a1); m = fmaxf(m, fmaxf(a0, a1));
        }
        #pragma unroll
        for (int o = 16; o; o >>= 1) m = fmaxf(m, __shfl_xor_sync(0xffffffffu, m, o));
        if (lane == 0) sm[w] = m;
        __syncthreads();
        float Mx = sm[0];
        #pragma unroll
        for (int i = 1; i < 8; i++) Mx = fmaxf(Mx, sm[i]);

        // pass 2: thresholded exp sum, warp-vote to skip dead groups
        float thr = Mx - 25.f;
        float s = 0.f;
        #pragma unroll
        for (int it = 0; it < 4; it++) {
            float a[8];
            DEC2(cur[it].x, vr[it][0], vr[it][1], a[0], a[1]);
            DEC2(cur[it].y, vr[it][2], vr[it][3], a[2], a[3]);
            DEC2(cur[it].z, vr[it][4], vr[it][5], a[4], a[5]);
            DEC2(cur[it].w, vr[it][6], vr[it][7], a[6], a[7]);
            float gm = fmaxf(fmaxf(fmaxf(a[0], a[1]), fmaxf(a[2], a[3])),
                             fmaxf(fmaxf(a[4], a[5]), fmaxf(a[6], a[7])));
            if (__ballot_sync(0xffffffffu, gm > thr)) {
                #pragma unroll
                for (int k = 0; k < 8; k++)
                    if (a[k] > thr) s += exp2f(a[k] - Mx);
            }
        }
        #pragma unroll
        for (int o = 16; o; o >>= 1) s += __shfl_xor_sync(0xffffffffu, s, o);
        if (lane == 0) ssum[w] = s;
        __syncthreads();

        if (tid == 0) {
            float S = ssum[0];
            #pragma unroll
            for (int i = 1; i < 8; i++) S += ssum[i];
            float lse2 = Mx + log2f(S);
            float val;
            if (mode) val = EPSLOGN - EPSLN2 * lse2;
            else      val = 0.5f * (vold[row0 + r] + EPSLOGN - EPSLN2 * lse2);
            vout[row0 + r] = val;
        }

        #pragma unroll
        for (int it = 0; it < 4; it++) cur[it] = nxt[it];
    }
    #undef DEC2
}

// ---------------- final scalar reduction ----------------
__global__ void final_kernel(float* out) {
    __shared__ double sh[32];
    double acc = 0.0;
    for (int i = threadIdx.x; i < N; i += 1024) {
        acc += (double)d_evec[0][i] - (double)d_evec[2][i]
             + (double)d_evec[1][i] - (double)d_evec[3][i];
    }
    #pragma unroll
    for (int o = 16; o; o >>= 1) acc += __shfl_down_sync(0xffffffffu, acc, o);
    int w = threadIdx.x >> 5, lane = threadIdx.x & 31;
    if (lane == 0) sh[w] = acc;
    __syncthreads();
    if (threadIdx.x < 32) {
        double a = sh[threadIdx.x];
        #pragma unroll
        for (int o = 16; o; o >>= 1) a += __shfl_down_sync(0xffffffffu, a, o);
        if (threadIdx.x == 0) out[0] = (float)(a / (double)N);
    }
}

// ---------------- launch ----------------
extern "C" void kernel_launch(void* const* d_in, const int* in_sizes, int n_in,
                              void* d_out, int out_size) {
    (void)in_sizes; (void)n_in; (void)out_size;
    const float* x  = (const float*)d_in[0];   // xt
    const float* pz = (const float*)d_in[1];   // xs

    rownorm_kernel<<<dim3(N / 8, 2), 256>>>(x, pz);
    init_kernel<<<(2 * 4 * N + 255) / 256, 256>>>();

    dim3 gg(64, 64);
    gemm_dist_kernel<<<gg, 256>>>(x, pz, 0);
    gemm_dist_kernel<<<gg, 256>>>(x, pz, 1);
    gemm_dist_kernel<<<gg, 256>>>(x, pz, 2);

    for (int it = 0; it < 50; ++it)
        lse_kernel<<<dim3(N / ROWS, 4), 256>>>(it & 1, 0);

    lse_kernel<<<dim3(N / ROWS, 4), 256>>>(0, 1);   // extrapolation (final vecs in slot 0)
    final_kernel<<<1, 1024>>>((float*)d_out);
}